// round 11
// baseline (speedup 1.0000x reference)
#include <cuda_runtime.h>
#include <cuda_fp16.h>
#include <cstdint>

#define BB 8
#define NN 2048
#define FIN 128
#define FOUT 64
#define JSPLIT 8
#define JLEN (NN / JSPLIT)   // 256

// ---- scratch (static device arrays are allowed) ----
__device__ float    g_f1[BB * NN];
__device__ float    g_f2[BB * NN];
__device__ __half   g_ht[BB * FOUT * NN];              // h^T fp16 [b][f][j]
__device__ unsigned g_adjbit[BB * NN * NN / 32];       // 4 MB bitmask
__device__ float    g_pout[JSPLIT * BB * NN * FOUT];   // 32 MB partial PV sums
__device__ float    g_pden[JSPLIT * BB * NN];          // partial denominators

__device__ __forceinline__ float ex2f(float x) {
    float y; asm("ex2.approx.f32 %0, %1;" : "=f"(y) : "f"(x)); return y;
}
__device__ __forceinline__ float tanhf_hw(float x) {
    float y; asm("tanh.approx.f32 %0, %1;" : "=f"(y) : "f"(x)); return y;
}
// w = exp(tanh(s)) = ex2(tanh(s) * log2(e)).  2 MUFU + 1 MUL.
__device__ __forceinline__ float gat_w(float s) {
    return ex2f(tanhf_hw(s) * 1.4426950408889634f);
}
__device__ __forceinline__ float eluf(float x) { return x > 0.f ? x : expm1f(x); }
__device__ __forceinline__ uint32_t packh2(float lo, float hi) {
    __half2 h = __floats2half2_rn(lo, hi);
    return *(uint32_t*)&h;
}
__device__ __forceinline__ uint32_t smem_u32(const void* p) {
    uint32_t a;
    asm("{ .reg .u64 t; cvta.to.shared.u64 t, %1; cvt.u32.u64 %0, t; }"
        : "=r"(a) : "l"(p));
    return a;
}
__device__ __forceinline__ void cp16(uint32_t dst, const void* src) {
    asm volatile("cp.async.cg.shared.global [%0], [%1], 16;"
                 :: "r"(dst), "l"(src) : "memory");
}

// ---------------------------------------------------------------------------
// Kernel A: h = x@W (f32), f1/f2 = h@a halves, h^T fp16 out, AND adjacency
// bit-pack overlapped with the FMA loop. Pack loads are software-pipelined
// one full iteration ahead; ballot words are captured into registers
// (word k4*8+p -> lane k4, slot p) and written as 2 coalesced STG.128.
// 512 CTAs x 256 thr, 32 h-rows/CTA; each warp packs 8192 adjacency ints.
// ---------------------------------------------------------------------------
#define HP 40   // hsT pitch in halves

__global__ __launch_bounds__(256) void k_proj(const float* __restrict__ x,
                                              const int* __restrict__ adj,
                                              const float* __restrict__ W,
                                              const float* __restrict__ a) {
    __shared__ float  Ws[FIN * FOUT];       // 32 KB
    __shared__ __half hsT[FOUT * HP];       // 5 KB

    const int tid  = threadIdx.x;
    const int lane = tid & 31;
    const int warp = tid >> 5;
    const int t    = lane & 15;
    const int hh   = lane >> 4;
    const int b    = blockIdx.x >> 6;
    const int jb   = (blockIdx.x & 63) * 32;

    // this warp packs 8192 consecutive adjacency ints -> 256 mask words
    const int* apack = adj + ((size_t)blockIdx.x * 65536 + warp * 8192) + lane;
    unsigned*  wout  = g_adjbit + (blockIdx.x * 2048 + warp * 256);

    {
        const float4* Wsrc = (const float4*)W;
        float4*       Wdst = (float4*)Ws;
#pragma unroll
        for (int c = 0; c < 8; ++c) Wdst[tid + 256 * c] = Wsrc[tid + 256 * c];
    }
    const float4 av1 = *(const float4*)(a + 4 * t);
    const float4 av2 = *(const float4*)(a + FOUT + 4 * t);
    __syncthreads();

    const float* xr = x + ((size_t)b * NN + jb + warp * 4) * FIN;
    float4 acc[4];
#pragma unroll
    for (int r = 0; r < 4; ++r) acc[r] = make_float4(0.f, 0.f, 0.f, 0.f);

    // pack pipeline: preload iteration 0
    int pv[8], nxt[8];
#pragma unroll
    for (int p = 0; p < 8; ++p) pv[p] = __ldg(apack + p * 32);
    unsigned msl[8];

#pragma unroll 4
    for (int k4 = 0; k4 < FIN / 4; ++k4) {
        // issue next iteration's pack loads FIRST (max distance to consumer)
        if (k4 + 1 < FIN / 4) {
#pragma unroll
            for (int p = 0; p < 8; ++p)
                nxt[p] = __ldg(apack + ((k4 + 1) * 8 + p) * 32);
        }

        const int k0 = k4 * 4 + hh * 2;
        float2 xv[4];
#pragma unroll
        for (int r = 0; r < 4; ++r)
            xv[r] = __ldg((const float2*)(xr + (size_t)r * FIN + k0));
        const float4 w0 = *(const float4*)&Ws[k0 * FOUT + 4 * t];
        const float4 w1 = *(const float4*)&Ws[(k0 + 1) * FOUT + 4 * t];
#pragma unroll
        for (int r = 0; r < 4; ++r) {
            acc[r].x = fmaf(xv[r].x, w0.x, acc[r].x);
            acc[r].y = fmaf(xv[r].x, w0.y, acc[r].y);
            acc[r].z = fmaf(xv[r].x, w0.z, acc[r].z);
            acc[r].w = fmaf(xv[r].x, w0.w, acc[r].w);
            acc[r].x = fmaf(xv[r].y, w1.x, acc[r].x);
            acc[r].y = fmaf(xv[r].y, w1.y, acc[r].y);
            acc[r].z = fmaf(xv[r].y, w1.z, acc[r].z);
            acc[r].w = fmaf(xv[r].y, w1.w, acc[r].w);
        }

        // ballot current iteration; word k4*8+p belongs to lane k4, slot p
#pragma unroll
        for (int p = 0; p < 8; ++p) {
            const unsigned m = __ballot_sync(0xffffffffu, pv[p] > 0);
            if (lane == k4) msl[p] = m;
        }
#pragma unroll
        for (int p = 0; p < 8; ++p) pv[p] = nxt[p];
    }

    // coalesced mask write: lane l owns words [8l, 8l+8)
    *(uint4*)(wout + lane * 8)     = make_uint4(msl[0], msl[1], msl[2], msl[3]);
    *(uint4*)(wout + lane * 8 + 4) = make_uint4(msl[4], msl[5], msl[6], msl[7]);

#pragma unroll
    for (int r = 0; r < 4; ++r) {
        acc[r].x += __shfl_xor_sync(0xffffffffu, acc[r].x, 16);
        acc[r].y += __shfl_xor_sync(0xffffffffu, acc[r].y, 16);
        acc[r].z += __shfl_xor_sync(0xffffffffu, acc[r].z, 16);
        acc[r].w += __shfl_xor_sync(0xffffffffu, acc[r].w, 16);
    }

#pragma unroll
    for (int r = 0; r < 4; ++r) {
        const int rowloc = warp * 4 + r;
        if (hh == 0) {
            hsT[(4 * t) * HP + rowloc]     = __float2half_rn(acc[r].x);
            hsT[(4 * t + 1) * HP + rowloc] = __float2half_rn(acc[r].y);
            hsT[(4 * t + 2) * HP + rowloc] = __float2half_rn(acc[r].z);
            hsT[(4 * t + 3) * HP + rowloc] = __float2half_rn(acc[r].w);
        }
        float p1 = acc[r].x * av1.x + acc[r].y * av1.y
                 + acc[r].z * av1.z + acc[r].w * av1.w;
        float p2 = acc[r].x * av2.x + acc[r].y * av2.y
                 + acc[r].z * av2.z + acc[r].w * av2.w;
#pragma unroll
        for (int d = 8; d; d >>= 1) {
            p1 += __shfl_xor_sync(0xffffffffu, p1, d);
            p2 += __shfl_xor_sync(0xffffffffu, p2, d);
        }
        if (lane == 0) {
            g_f1[b * NN + jb + rowloc] = p1;
            g_f2[b * NN + jb + rowloc] = p2;
        }
    }
    __syncthreads();

    {
        const int feat = tid >> 2;
        const int seg  = tid & 3;
        const uint4 v = *(const uint4*)&hsT[feat * HP + seg * 8];
        *(uint4*)(g_ht + ((size_t)(b * FOUT + feat)) * NN + jb + seg * 8) = v;
    }
}

// ---------------------------------------------------------------------------
// Kernel B: fused GAT attention on mma.sync.m16n8k16, j-split x8, bitmask.
// Grid (16, 8, 8) = 1024 CTAs; 256 thr = 8 warps; warp owns 16 i x 64 f over
// a 256-j slice, 8 stages of 32 j. Masks staged once (4 KB); h^T tiles
// double-buffered via cp.async. 4 CTAs/SM.
// ---------------------------------------------------------------------------
#define HPITCH 40            // halves per h-tile row
#define MPITCH 12            // words per mask row
#define NST (JLEN / 32)      // 8 stages

__global__ __launch_bounds__(256, 4) void k_attn() {
    __shared__ float                   f2s[JLEN];                // 1 KB
    __shared__ __align__(16) __half    hTs[2][FOUT * HPITCH];    // 10 KB
    __shared__ __align__(16) unsigned  msk[128 * MPITCH];        // 6 KB

    const int tid   = threadIdx.x;
    const int warp  = tid >> 5;
    const int lane  = tid & 31;
    const int t     = lane & 3;
    const int g     = lane >> 2;
    const int b     = blockIdx.z;
    const int split = blockIdx.y;
    const int i0    = blockIdx.x * 128;
    const int jb    = split * JLEN;

    const int rloc0 = warp * 16 + g;
    const int r0    = i0 + rloc0;
    const int r1    = r0 + 8;

    const float f1_0 = g_f1[b * NN + r0];
    const float f1_1 = g_f1[b * NN + r1];
    f2s[tid] = g_f2[b * NN + jb + tid];

    // ---- stage masks: 128 rows x 8 words, uint4 per thread ----
    {
        const int row  = tid >> 1;
        const int part = tid & 1;
        const uint4 v = *(const uint4*)(g_adjbit +
            ((size_t)b * NN + i0 + row) * (NN / 32) + split * NST + part * 4);
        *(uint4*)&msk[row * MPITCH + part * 4] = v;
    }

    // ---- h^T cp.async setup: 64 feats x 4 segs of 16B, 1 per thread ----
    const int hf = tid >> 2;
    const int sg = tid & 3;
    const __half* hsrc = g_ht + ((size_t)(b * FOUT + hf)) * NN + jb + sg * 8;
    const uint32_t hdst = smem_u32(&hTs[0][hf * HPITCH + sg * 8]);
    const uint32_t hbuf = (uint32_t)(FOUT * HPITCH * 2);

    cp16(hdst, hsrc);
    asm volatile("cp.async.commit_group;" ::: "memory");

    float acc[32];
#pragma unroll
    for (int k = 0; k < 32; ++k) acc[k] = 0.f;
    float ds0 = 0.f, ds1 = 0.f;

    for (int s = 0; s < NST; ++s) {
        if (s + 1 < NST) {
            cp16(hdst + (((s + 1) & 1) ? hbuf : 0u), hsrc + (s + 1) * 32);
            asm volatile("cp.async.commit_group;" ::: "memory");
            asm volatile("cp.async.wait_group 1;" ::: "memory");
        } else {
            asm volatile("cp.async.wait_group 0;" ::: "memory");
        }
        __syncthreads();
        const __half* hcur = hTs[s & 1];

        const unsigned word0 = msk[rloc0 * MPITCH + s];
        const unsigned word1 = msk[(rloc0 + 8) * MPITCH + s];

#pragma unroll
        for (int kk = 0; kk < 2; ++kk) {
            const int j0 = s * 32 + kk * 16;
            const unsigned ua = word0 >> (kk * 16 + 2 * t);
            const unsigned ub = word1 >> (kk * 16 + 2 * t);

            const float2 flo = *(const float2*)&f2s[j0 + 2 * t];
            const float2 fhi = *(const float2*)&f2s[j0 + 8 + 2 * t];

            float w00 = gat_w(f1_0 + flo.x), w01 = gat_w(f1_0 + flo.y);
            float w02 = gat_w(f1_0 + fhi.x), w03 = gat_w(f1_0 + fhi.y);
            float w10 = gat_w(f1_1 + flo.x), w11 = gat_w(f1_1 + flo.y);
            float w12 = gat_w(f1_1 + fhi.x), w13 = gat_w(f1_1 + fhi.y);
            w00 = (ua & 1u)     ? w00 : 0.f;
            w01 = (ua & 2u)     ? w01 : 0.f;
            w02 = (ua & 0x100u) ? w02 : 0.f;
            w03 = (ua & 0x200u) ? w03 : 0.f;
            w10 = (ub & 1u)     ? w10 : 0.f;
            w11 = (ub & 2u)     ? w11 : 0.f;
            w12 = (ub & 0x100u) ? w12 : 0.f;
            w13 = (ub & 0x200u) ? w13 : 0.f;
            ds0 += (w00 + w01) + (w02 + w03);
            ds1 += (w10 + w11) + (w12 + w13);

            const uint32_t A0 = packh2(w00, w01);
            const uint32_t A1 = packh2(w10, w11);
            const uint32_t A2 = packh2(w02, w03);
            const uint32_t A3 = packh2(w12, w13);

            const int ko = kk * 16 + 2 * t;
#pragma unroll
            for (int nb = 0; nb < 8; ++nb) {
                const __half* bp = hcur + (nb * 8 + g) * HPITCH + ko;
                const uint32_t B0 = *(const uint32_t*)bp;
                const uint32_t B1 = *(const uint32_t*)(bp + 8);
                float* c = acc + nb * 4;
                asm volatile(
                    "mma.sync.aligned.m16n8k16.row.col.f32.f16.f16.f32 "
                    "{%0,%1,%2,%3}, {%4,%5,%6,%7}, {%8,%9}, {%0,%1,%2,%3};"
                    : "+f"(c[0]), "+f"(c[1]), "+f"(c[2]), "+f"(c[3])
                    : "r"(A0), "r"(A1), "r"(A2), "r"(A3), "r"(B0), "r"(B1));
            }
        }
        __syncthreads();
    }

    ds0 += __shfl_xor_sync(0xffffffffu, ds0, 1);
    ds0 += __shfl_xor_sync(0xffffffffu, ds0, 2);
    ds1 += __shfl_xor_sync(0xffffffffu, ds1, 1);
    ds1 += __shfl_xor_sync(0xffffffffu, ds1, 2);

    const size_t pbase = (size_t)(split * BB + b);
    if (t == 0) {
        g_pden[pbase * NN + r0] = ds0;
        g_pden[pbase * NN + r1] = ds1;
    }
    float* o0 = g_pout + (pbase * NN + r0) * FOUT;
    float* o1 = g_pout + (pbase * NN + r1) * FOUT;
#pragma unroll
    for (int nb = 0; nb < 8; ++nb) {
        *(float2*)(o0 + nb * 8 + 2 * t) = make_float2(acc[nb * 4 + 0], acc[nb * 4 + 1]);
        *(float2*)(o1 + nb * 8 + 2 * t) = make_float2(acc[nb * 4 + 2], acc[nb * 4 + 3]);
    }
}

// ---------------------------------------------------------------------------
// Kernel C: combine partials -> divide -> ELU -> out. Memory-bound.
// ---------------------------------------------------------------------------
__global__ __launch_bounds__(256) void k_comb(float* __restrict__ out) {
    const int idx = blockIdx.x * 256 + threadIdx.x;
    const int row = idx >> 4;
    const int seg = idx & 15;

    float den = 0.f;
#pragma unroll
    for (int s = 0; s < JSPLIT; ++s) den += g_pden[(size_t)s * BB * NN + row];
    const float inv = 1.0f / den;

    float4 v = make_float4(0.f, 0.f, 0.f, 0.f);
#pragma unroll
    for (int s = 0; s < JSPLIT; ++s) {
        const float4 p = *(const float4*)(g_pout +
            ((size_t)s * BB * NN + row) * FOUT + seg * 4);
        v.x += p.x; v.y += p.y; v.z += p.z; v.w += p.w;
    }
    v.x = eluf(v.x * inv); v.y = eluf(v.y * inv);
    v.z = eluf(v.z * inv); v.w = eluf(v.w * inv);
    *(float4*)(out + (size_t)row * FOUT + seg * 4) = v;
}

// ---------------------------------------------------------------------------
extern "C" void kernel_launch(void* const* d_in, const int* in_sizes, int n_in,
                              void* d_out, int out_size) {
    const float* x   = (const float*)d_in[0];
    const int*   adj = (const int*)d_in[1];
    const float* W   = (const float*)d_in[2];
    const float* a   = (const float*)d_in[3];
    float*       out = (float*)d_out;

    k_proj<<<BB * NN / 32, 256>>>(x, adj, W, a);
    k_attn<<<dim3(16, JSPLIT, BB), 256>>>();
    k_comb<<<BB * NN * 16 / 256, 256>>>(out);
}

// round 13
// speedup vs baseline: 1.2061x; 1.2061x over previous
#include <cuda_runtime.h>
#include <cuda_fp16.h>
#include <cstdint>

#define BB 8
#define NN 2048
#define FIN 128
#define FOUT 64
#define JSPLIT 8
#define JLEN (NN / JSPLIT)   // 256

// ---- scratch (static device arrays are allowed) ----
__device__ float    g_f1[BB * NN];
__device__ float    g_f2[BB * NN];
__device__ __half   g_ht[BB * FOUT * NN];              // h^T fp16 [b][f][j]
__device__ unsigned g_adjbit[BB * NN * NN / 32];       // 4 MB bitmask
__device__ float    g_pout[JSPLIT * BB * NN * FOUT];   // 32 MB partial PV sums
__device__ float    g_pden[JSPLIT * BB * NN];          // partial denominators

__device__ __forceinline__ float ex2f(float x) {
    float y; asm("ex2.approx.f32 %0, %1;" : "=f"(y) : "f"(x)); return y;
}
__device__ __forceinline__ float tanhf_hw(float x) {
    float y; asm("tanh.approx.f32 %0, %1;" : "=f"(y) : "f"(x)); return y;
}
// w = exp(tanh(s)) = ex2(tanh(s) * log2(e)).  2 MUFU + 1 MUL.
__device__ __forceinline__ float gat_w(float s) {
    return ex2f(tanhf_hw(s) * 1.4426950408889634f);
}
__device__ __forceinline__ float eluf(float x) { return x > 0.f ? x : expm1f(x); }
__device__ __forceinline__ uint32_t packh2(float lo, float hi) {
    __half2 h = __floats2half2_rn(lo, hi);
    return *(uint32_t*)&h;
}
__device__ __forceinline__ uint32_t smem_u32(const void* p) {
    uint32_t a;
    asm("{ .reg .u64 t; cvta.to.shared.u64 t, %1; cvt.u32.u64 %0, t; }"
        : "=r"(a) : "l"(p));
    return a;
}
__device__ __forceinline__ void cp16(uint32_t dst, const void* src) {
    asm volatile("cp.async.cg.shared.global [%0], [%1], 16;"
                 :: "r"(dst), "l"(src) : "memory");
}

// ---------------------------------------------------------------------------
// Kernel A (heterogeneous): 1024 CTAs x 256 thr.
//   even blockIdx -> PROJ role (512 CTAs): h = x@W, f1/f2, h^T fp16  (R9 code)
//   odd  blockIdx -> PACK role (512 CTAs): adjacency int32 -> bitmask stream
// Parity interleave puts both roles on every SM so the pack's 134 MB DRAM
// stream overlaps the proj CTAs' FMA/LDS work.
// PACK quota: 2048 words per CTA (512 * 2048 = 1,048,576 = BB*NN*NN/32).
// ---------------------------------------------------------------------------
#define HP 40   // hsT pitch in halves

__global__ __launch_bounds__(256) void k_projpack(const float* __restrict__ x,
                                                  const int* __restrict__ adj,
                                                  const float* __restrict__ W,
                                                  const float* __restrict__ a) {
    __shared__ float  Ws[FIN * FOUT];       // 32 KB
    __shared__ __half hsT[FOUT * HP];       // 5 KB

    const int tid  = threadIdx.x;
    const int lane = tid & 31;
    const int warp = tid >> 5;
    const int pid  = blockIdx.x >> 1;

    if (blockIdx.x & 1) {
        // ================= PACK role =================
        // CTA packs 2048 mask words (65536 ints); warp packs 256 words.
        const size_t wb  = (size_t)pid * 2048 + warp * 256;
        const int*   src = adj + wb * 32 + lane;
        unsigned*    dst = g_adjbit + wb;

#pragma unroll
        for (int grp = 0; grp < 8; ++grp) {
            unsigned word = 0;
#pragma unroll
            for (int i = 0; i < 32; ++i) {
                const int v = __ldg(src + (size_t)(grp * 32 + i) * 32);
                const unsigned m = __ballot_sync(0xffffffffu, v > 0);
                if (lane == i) word = m;
            }
            dst[grp * 32 + lane] = word;
        }
        return;
    }

    // ================= PROJ role =================
    const int t  = lane & 15;
    const int hh = lane >> 4;
    const int b  = pid >> 6;
    const int jb = (pid & 63) * 32;

    {
        const float4* Wsrc = (const float4*)W;
        float4*       Wdst = (float4*)Ws;
#pragma unroll
        for (int c = 0; c < 8; ++c) Wdst[tid + 256 * c] = Wsrc[tid + 256 * c];
    }
    const float4 av1 = *(const float4*)(a + 4 * t);
    const float4 av2 = *(const float4*)(a + FOUT + 4 * t);
    __syncthreads();

    const float* xr = x + ((size_t)b * NN + jb + warp * 4) * FIN;
    float4 acc[4];
#pragma unroll
    for (int r = 0; r < 4; ++r) acc[r] = make_float4(0.f, 0.f, 0.f, 0.f);

#pragma unroll 4
    for (int k4 = 0; k4 < FIN / 4; ++k4) {
        const int k0 = k4 * 4 + hh * 2;
        float2 xv[4];
#pragma unroll
        for (int r = 0; r < 4; ++r)
            xv[r] = __ldg((const float2*)(xr + (size_t)r * FIN + k0));
        const float4 w0 = *(const float4*)&Ws[k0 * FOUT + 4 * t];
        const float4 w1 = *(const float4*)&Ws[(k0 + 1) * FOUT + 4 * t];
#pragma unroll
        for (int r = 0; r < 4; ++r) {
            acc[r].x = fmaf(xv[r].x, w0.x, acc[r].x);
            acc[r].y = fmaf(xv[r].x, w0.y, acc[r].y);
            acc[r].z = fmaf(xv[r].x, w0.z, acc[r].z);
            acc[r].w = fmaf(xv[r].x, w0.w, acc[r].w);
            acc[r].x = fmaf(xv[r].y, w1.x, acc[r].x);
            acc[r].y = fmaf(xv[r].y, w1.y, acc[r].y);
            acc[r].z = fmaf(xv[r].y, w1.z, acc[r].z);
            acc[r].w = fmaf(xv[r].y, w1.w, acc[r].w);
        }
    }

#pragma unroll
    for (int r = 0; r < 4; ++r) {
        acc[r].x += __shfl_xor_sync(0xffffffffu, acc[r].x, 16);
        acc[r].y += __shfl_xor_sync(0xffffffffu, acc[r].y, 16);
        acc[r].z += __shfl_xor_sync(0xffffffffu, acc[r].z, 16);
        acc[r].w += __shfl_xor_sync(0xffffffffu, acc[r].w, 16);
    }

#pragma unroll
    for (int r = 0; r < 4; ++r) {
        const int rowloc = warp * 4 + r;
        if (hh == 0) {
            hsT[(4 * t) * HP + rowloc]     = __float2half_rn(acc[r].x);
            hsT[(4 * t + 1) * HP + rowloc] = __float2half_rn(acc[r].y);
            hsT[(4 * t + 2) * HP + rowloc] = __float2half_rn(acc[r].z);
            hsT[(4 * t + 3) * HP + rowloc] = __float2half_rn(acc[r].w);
        }
        float p1 = acc[r].x * av1.x + acc[r].y * av1.y
                 + acc[r].z * av1.z + acc[r].w * av1.w;
        float p2 = acc[r].x * av2.x + acc[r].y * av2.y
                 + acc[r].z * av2.z + acc[r].w * av2.w;
#pragma unroll
        for (int d = 8; d; d >>= 1) {
            p1 += __shfl_xor_sync(0xffffffffu, p1, d);
            p2 += __shfl_xor_sync(0xffffffffu, p2, d);
        }
        if (lane == 0) {
            g_f1[b * NN + jb + rowloc] = p1;
            g_f2[b * NN + jb + rowloc] = p2;
        }
    }
    __syncthreads();

    {
        const int feat = tid >> 2;
        const int seg  = tid & 3;
        const uint4 v = *(const uint4*)&hsT[feat * HP + seg * 8];
        *(uint4*)(g_ht + ((size_t)(b * FOUT + feat)) * NN + jb + seg * 8) = v;
    }
}

// ---------------------------------------------------------------------------
// Kernel B: fused GAT attention on mma.sync.m16n8k16, j-split x8, bitmask.
// Grid (16, 8, 8) = 1024 CTAs; 256 thr = 8 warps; warp owns 16 i x 64 f over
// a 256-j slice, 8 stages of 32 j. Masks staged once (4 KB); h^T tiles
// double-buffered via cp.async. 4 CTAs/SM.
// ---------------------------------------------------------------------------
#define HPITCH 40            // halves per h-tile row
#define MPITCH 12            // words per mask row
#define NST (JLEN / 32)      // 8 stages

__global__ __launch_bounds__(256, 4) void k_attn() {
    __shared__ float                   f2s[JLEN];                // 1 KB
    __shared__ __align__(16) __half    hTs[2][FOUT * HPITCH];    // 10 KB
    __shared__ __align__(16) unsigned  msk[128 * MPITCH];        // 6 KB

    const int tid   = threadIdx.x;
    const int warp  = tid >> 5;
    const int lane  = tid & 31;
    const int t     = lane & 3;
    const int g     = lane >> 2;
    const int b     = blockIdx.z;
    const int split = blockIdx.y;
    const int i0    = blockIdx.x * 128;
    const int jb    = split * JLEN;

    const int rloc0 = warp * 16 + g;
    const int r0    = i0 + rloc0;
    const int r1    = r0 + 8;

    const float f1_0 = g_f1[b * NN + r0];
    const float f1_1 = g_f1[b * NN + r1];
    f2s[tid] = g_f2[b * NN + jb + tid];

    // ---- stage masks: 128 rows x 8 words, uint4 per thread ----
    {
        const int row  = tid >> 1;
        const int part = tid & 1;
        const uint4 v = *(const uint4*)(g_adjbit +
            ((size_t)b * NN + i0 + row) * (NN / 32) + split * NST + part * 4);
        *(uint4*)&msk[row * MPITCH + part * 4] = v;
    }

    // ---- h^T cp.async setup: 64 feats x 4 segs of 16B, 1 per thread ----
    const int hf = tid >> 2;
    const int sg = tid & 3;
    const __half* hsrc = g_ht + ((size_t)(b * FOUT + hf)) * NN + jb + sg * 8;
    const uint32_t hdst = smem_u32(&hTs[0][hf * HPITCH + sg * 8]);
    const uint32_t hbuf = (uint32_t)(FOUT * HPITCH * 2);

    cp16(hdst, hsrc);
    asm volatile("cp.async.commit_group;" ::: "memory");

    float acc[32];
#pragma unroll
    for (int k = 0; k < 32; ++k) acc[k] = 0.f;
    float ds0 = 0.f, ds1 = 0.f;

    for (int s = 0; s < NST; ++s) {
        if (s + 1 < NST) {
            cp16(hdst + (((s + 1) & 1) ? hbuf : 0u), hsrc + (s + 1) * 32);
            asm volatile("cp.async.commit_group;" ::: "memory");
            asm volatile("cp.async.wait_group 1;" ::: "memory");
        } else {
            asm volatile("cp.async.wait_group 0;" ::: "memory");
        }
        __syncthreads();
        const __half* hcur = hTs[s & 1];

        const unsigned word0 = msk[rloc0 * MPITCH + s];
        const unsigned word1 = msk[(rloc0 + 8) * MPITCH + s];

#pragma unroll
        for (int kk = 0; kk < 2; ++kk) {
            const int j0 = s * 32 + kk * 16;
            const unsigned ua = word0 >> (kk * 16 + 2 * t);
            const unsigned ub = word1 >> (kk * 16 + 2 * t);

            const float2 flo = *(const float2*)&f2s[j0 + 2 * t];
            const float2 fhi = *(const float2*)&f2s[j0 + 8 + 2 * t];

            float w00 = gat_w(f1_0 + flo.x), w01 = gat_w(f1_0 + flo.y);
            float w02 = gat_w(f1_0 + fhi.x), w03 = gat_w(f1_0 + fhi.y);
            float w10 = gat_w(f1_1 + flo.x), w11 = gat_w(f1_1 + flo.y);
            float w12 = gat_w(f1_1 + fhi.x), w13 = gat_w(f1_1 + fhi.y);
            w00 = (ua & 1u)     ? w00 : 0.f;
            w01 = (ua & 2u)     ? w01 : 0.f;
            w02 = (ua & 0x100u) ? w02 : 0.f;
            w03 = (ua & 0x200u) ? w03 : 0.f;
            w10 = (ub & 1u)     ? w10 : 0.f;
            w11 = (ub & 2u)     ? w11 : 0.f;
            w12 = (ub & 0x100u) ? w12 : 0.f;
            w13 = (ub & 0x200u) ? w13 : 0.f;
            ds0 += (w00 + w01) + (w02 + w03);
            ds1 += (w10 + w11) + (w12 + w13);

            const uint32_t A0 = packh2(w00, w01);
            const uint32_t A1 = packh2(w10, w11);
            const uint32_t A2 = packh2(w02, w03);
            const uint32_t A3 = packh2(w12, w13);

            const int ko = kk * 16 + 2 * t;
#pragma unroll
            for (int nb = 0; nb < 8; ++nb) {
                const __half* bp = hcur + (nb * 8 + g) * HPITCH + ko;
                const uint32_t B0 = *(const uint32_t*)bp;
                const uint32_t B1 = *(const uint32_t*)(bp + 8);
                float* c = acc + nb * 4;
                asm volatile(
                    "mma.sync.aligned.m16n8k16.row.col.f32.f16.f16.f32 "
                    "{%0,%1,%2,%3}, {%4,%5,%6,%7}, {%8,%9}, {%0,%1,%2,%3};"
                    : "+f"(c[0]), "+f"(c[1]), "+f"(c[2]), "+f"(c[3])
                    : "r"(A0), "r"(A1), "r"(A2), "r"(A3), "r"(B0), "r"(B1));
            }
        }
        __syncthreads();
    }

    ds0 += __shfl_xor_sync(0xffffffffu, ds0, 1);
    ds0 += __shfl_xor_sync(0xffffffffu, ds0, 2);
    ds1 += __shfl_xor_sync(0xffffffffu, ds1, 1);
    ds1 += __shfl_xor_sync(0xffffffffu, ds1, 2);

    const size_t pbase = (size_t)(split * BB + b);
    if (t == 0) {
        g_pden[pbase * NN + r0] = ds0;
        g_pden[pbase * NN + r1] = ds1;
    }
    float* o0 = g_pout + (pbase * NN + r0) * FOUT;
    float* o1 = g_pout + (pbase * NN + r1) * FOUT;
#pragma unroll
    for (int nb = 0; nb < 8; ++nb) {
        *(float2*)(o0 + nb * 8 + 2 * t) = make_float2(acc[nb * 4 + 0], acc[nb * 4 + 1]);
        *(float2*)(o1 + nb * 8 + 2 * t) = make_float2(acc[nb * 4 + 2], acc[nb * 4 + 3]);
    }
}

// ---------------------------------------------------------------------------
// Kernel C: combine partials -> divide -> ELU -> out. Memory-bound.
// ---------------------------------------------------------------------------
__global__ __launch_bounds__(256) void k_comb(float* __restrict__ out) {
    const int idx = blockIdx.x * 256 + threadIdx.x;
    const int row = idx >> 4;
    const int seg = idx & 15;

    float den = 0.f;
#pragma unroll
    for (int s = 0; s < JSPLIT; ++s) den += g_pden[(size_t)s * BB * NN + row];
    const float inv = 1.0f / den;

    float4 v = make_float4(0.f, 0.f, 0.f, 0.f);
#pragma unroll
    for (int s = 0; s < JSPLIT; ++s) {
        const float4 p = *(const float4*)(g_pout +
            ((size_t)s * BB * NN + row) * FOUT + seg * 4);
        v.x += p.x; v.y += p.y; v.z += p.z; v.w += p.w;
    }
    v.x = eluf(v.x * inv); v.y = eluf(v.y * inv);
    v.z = eluf(v.z * inv); v.w = eluf(v.w * inv);
    *(float4*)(out + (size_t)row * FOUT + seg * 4) = v;
}

// ---------------------------------------------------------------------------
extern "C" void kernel_launch(void* const* d_in, const int* in_sizes, int n_in,
                              void* d_out, int out_size) {
    const float* x   = (const float*)d_in[0];
    const int*   adj = (const int*)d_in[1];
    const float* W   = (const float*)d_in[2];
    const float* a   = (const float*)d_in[3];
    float*       out = (float*)d_out;

    k_projpack<<<BB * NN / 16, 256>>>(x, adj, W, a);
    k_attn<<<dim3(16, JSPLIT, BB), 256>>>();
    k_comb<<<BB * NN * 16 / 256, 256>>>(out);
}